// round 15
// baseline (speedup 1.0000x reference)
#include <cuda_runtime.h>
#include <cuda_fp16.h>
#include <math.h>
#include <stdint.h>

#define BATCH 4
#define SEQ   2048
#define DIM   1024
#define NH    16
#define HDIM  64
#define MTOT  (BATCH*SEQ)     // 8192
#define NQKV  (3*DIM)         // 3072

// ---------------- scratch (device globals; no allocations allowed) ----------
static __device__ __half g_hid_h[(size_t)MTOT*DIM];
static __device__ __half g_wqkv_h[(size_t)NQKV*DIM];
static __device__ __half g_wo_h[(size_t)DIM*DIM];
static __device__ __half g_qh[(size_t)BATCH*NH*SEQ*HDIM];   // [bh][s][d] (scaled)
static __device__ __half g_kh[(size_t)BATCH*NH*SEQ*HDIM];   // [bh][s][d]
static __device__ __half g_vh[(size_t)BATCH*NH*SEQ*HDIM];   // [bh][s][d]
static __device__ __half g_attn_h[(size_t)MTOT*DIM];        // [b*S+s][h*64+d]
static __device__ float  g_cos[SEQ*32];
static __device__ float  g_sin[SEQ*32];

// scale folded into Q: (1/sqrt(64)) * log2(e)
#define QFAC 0.18033688011112042f

// ---------------- small kernels ----------------------------------------------
__global__ void rope_table_kernel() {
    int idx = blockIdx.x * blockDim.x + threadIdx.x;
    if (idx >= SEQ*32) return;
    int s = idx >> 5;
    int f = idx & 31;
    float inv_freq = (float)exp(-((double)(2*f) / 64.0) * log(10000.0));
    float ang = (float)s * inv_freq;
    float sn, cs;
    sincosf(ang, &sn, &cs);
    g_cos[idx] = cs;
    g_sin[idx] = sn;
}

// merged fp32 -> fp16 bulk convert, MLP=4 (hidden | Wqkv | Wo)
#define N4_HID  (MTOT*DIM/4)
#define N4_WQKV (NQKV*DIM/4)
#define N4_WO   (DIM*DIM/4)
#define N4_ALL  (N4_HID + N4_WQKV + N4_WO)      // 3145728
__global__ void f2h_all(const float* __restrict__ hid,
                        const float* __restrict__ wq,
                        const float* __restrict__ wo) {
    const int base = blockIdx.x * (256 * 4) + threadIdx.x;
    float4 v[4];
    __half* dsts[4];
    int js[4];
    #pragma unroll
    for (int u = 0; u < 4; ++u) {
        int j = base + u * 256;
        const float* src; __half* dst;
        if (j < N4_HID)                   { src = hid; dst = g_hid_h; }
        else if ((j -= N4_HID) < N4_WQKV) { src = wq;  dst = g_wqkv_h; }
        else { j -= N4_WQKV;                src = wo;  dst = g_wo_h; }
        dsts[u] = dst; js[u] = j;
        v[u] = ((const float4*)src)[j];
    }
    #pragma unroll
    for (int u = 0; u < 4; ++u) {
        __half2 h0 = __floats2half2_rn(v[u].x, v[u].y);
        __half2 h1 = __floats2half2_rn(v[u].z, v[u].w);
        ((uint2*)dsts[u])[js[u]] = make_uint2(*(uint32_t*)&h0, *(uint32_t*)&h1);
    }
}

// ---------------- asm helpers -------------------------------------------------
__device__ __forceinline__ uint32_t smem_u32(const void* p) {
    uint32_t a;
    asm("{ .reg .u64 t; cvta.to.shared.u64 t, %1; cvt.u32.u64 %0, t; }" : "=r"(a) : "l"(p));
    return a;
}
__device__ __forceinline__ uint32_t packh2(float hi, float lo) {
    uint32_t r;
    asm("cvt.rn.f16x2.f32 %0, %1, %2;" : "=r"(r) : "f"(hi), "f"(lo));
    return r;
}
// 2-wide fp16 exp2
__device__ __forceinline__ uint32_t h2exp2(uint32_t x) {
    uint32_t y;
    asm("ex2.approx.f16x2 %0, %1;" : "=r"(y) : "r"(x));
    return y;
}
// fp32-accum mma
__device__ __forceinline__ void mma16816(float c[4], const uint32_t a[4],
                                         uint32_t b0, uint32_t b1) {
    asm volatile(
        "mma.sync.aligned.m16n8k16.row.col.f32.f16.f16.f32 "
        "{%0,%1,%2,%3},{%4,%5,%6,%7},{%8,%9},{%0,%1,%2,%3};"
        : "+f"(c[0]), "+f"(c[1]), "+f"(c[2]), "+f"(c[3])
        : "r"(a[0]), "r"(a[1]), "r"(a[2]), "r"(a[3]), "r"(b0), "r"(b1));
}
// fp16-accum mma: C/D packed f16x2 {row g | row g+8}
__device__ __forceinline__ void mma16816h(uint32_t c[2], const uint32_t a[4],
                                          uint32_t b0, uint32_t b1) {
    asm volatile(
        "mma.sync.aligned.m16n8k16.row.col.f16.f16.f16.f16 "
        "{%0,%1},{%2,%3,%4,%5},{%6,%7},{%0,%1};"
        : "+r"(c[0]), "+r"(c[1])
        : "r"(a[0]), "r"(a[1]), "r"(a[2]), "r"(a[3]), "r"(b0), "r"(b1));
}
__device__ __forceinline__ void ldsm4(uint32_t r[4], uint32_t addr) {
    asm volatile("ldmatrix.sync.aligned.m8n8.x4.shared.b16 {%0,%1,%2,%3}, [%4];"
        : "=r"(r[0]), "=r"(r[1]), "=r"(r[2]), "=r"(r[3]) : "r"(addr));
}
__device__ __forceinline__ void ldsm4t(uint32_t r[4], uint32_t addr) {
    asm volatile("ldmatrix.sync.aligned.m8n8.x4.trans.shared.b16 {%0,%1,%2,%3}, [%4];"
        : "=r"(r[0]), "=r"(r[1]), "=r"(r[2]), "=r"(r[3]) : "r"(addr));
}
__device__ __forceinline__ void cpa16(uint32_t dst, const void* src) {
    asm volatile("cp.async.cg.shared.global [%0], [%1], 16;" :: "r"(dst), "l"(src));
}
#define CP_COMMIT() asm volatile("cp.async.commit_group;" ::: "memory")
template<int N> __device__ __forceinline__ void cp_wait() {
    asm volatile("cp.async.wait_group %0;" :: "n"(N) : "memory");
}

// smem tile: rows of 64 halves (128B), chunk(16B) swizzle: ch ^ (row&7)
__device__ __forceinline__ uint32_t swz(int row, int ch) {
    return (uint32_t)(row * 128 + ((ch ^ (row & 7)) << 4));
}

extern __shared__ char dyn_sm[];

// ---------------- fp16 tensor-core NT GEMM (round-11, known good) ------------
// C[M,N] = A[M,1024] * B[N,1024]^T (+bias). Tile 128x128, 8 warps (4m x 2n),
// warp tile 32x64, k-stage 64, 2 smem stages, 2 CTAs/SM.
// smem: A bufs @0/16384, B bufs @32768/49152 (16KB each) = 64KB dynamic.
template<int MODE>
__global__ void __launch_bounds__(256, 2)
gemm_h(const float* __restrict__ bias, float* __restrict__ C)
{
    const __half* Ah = (MODE == 1) ? g_hid_h : g_attn_h;
    const __half* Bh = (MODE == 1) ? g_wqkv_h : g_wo_h;

    const uint32_t sb = smem_u32(dyn_sm);
    const int tid  = threadIdx.x;
    const int w    = tid >> 5;
    const int lane = tid & 31;
    const int g    = lane >> 2;
    const int t4   = lane & 3;
    const int wm0  = (w >> 1) * 32;
    const int wn0  = (w & 1) * 64;
    const int m0   = blockIdx.y * 128;
    const int n0   = blockIdx.x * 128;

    const int crow = tid >> 3;          // 0..31 (staging base row)
    const int cch  = tid & 7;

    const int lrA = (lane & 7) + ((lane >> 3) & 1) * 8;
    const int lhA = lane >> 4;
    const int lrB = (lane & 7) + ((lane >> 4) & 1) * 8;
    const int lhB = (lane >> 3) & 1;

    float acc[2][8][4] = {};

    {   // prologue: stage k0=0 into buf 0
        #pragma unroll
        for (int r = 0; r < 4; ++r) {
            int row = crow + 32 * r;
            cpa16(sb + swz(row, cch),          Ah + (size_t)(m0 + row) * 1024 + cch * 8);
            cpa16(sb + 32768u + swz(row, cch), Bh + (size_t)(n0 + row) * 1024 + cch * 8);
        }
        CP_COMMIT();
    }

    #pragma unroll 1
    for (int it = 0; it < 16; ++it) {
        const int buf = it & 1;
        if (it < 15) {
            const int k0 = (it + 1) * 64;
            const uint32_t bo = (uint32_t)(buf ^ 1) * 16384u;
            #pragma unroll
            for (int r = 0; r < 4; ++r) {
                int row = crow + 32 * r;
                cpa16(sb + bo + swz(row, cch),
                      Ah + (size_t)(m0 + row) * 1024 + k0 + cch * 8);
                cpa16(sb + 32768u + bo + swz(row, cch),
                      Bh + (size_t)(n0 + row) * 1024 + k0 + cch * 8);
            }
            CP_COMMIT();
            cp_wait<1>();
        } else {
            cp_wait<0>();
        }
        __syncthreads();

        const uint32_t Ab = sb + (uint32_t)buf * 16384u;
        const uint32_t Bb = sb + 32768u + (uint32_t)buf * 16384u;
        #pragma unroll
        for (int kc = 0; kc < 4; ++kc) {
            uint32_t a[2][4];
            #pragma unroll
            for (int mi = 0; mi < 2; ++mi)
                ldsm4(a[mi], Ab + swz(wm0 + mi * 16 + lrA, kc * 2 + lhA));
            #pragma unroll
            for (int np = 0; np < 4; ++np) {
                uint32_t b4[4];
                ldsm4(b4, Bb + swz(wn0 + np * 16 + lrB, kc * 2 + lhB));
                #pragma unroll
                for (int mi = 0; mi < 2; ++mi) {
                    mma16816(acc[mi][2 * np],     a[mi], b4[0], b4[1]);
                    mma16816(acc[mi][2 * np + 1], a[mi], b4[2], b4[3]);
                }
            }
        }
        __syncthreads();
    }

    // ---- epilogues ----
    if (MODE == 0) {
        #pragma unroll
        for (int nj = 0; nj < 8; ++nj) {
            const int col = n0 + wn0 + nj * 8 + 2 * t4;
            const float2 bj = *(const float2*)(bias + col);
            #pragma unroll
            for (int mi = 0; mi < 2; ++mi)
                #pragma unroll
                for (int rs = 0; rs < 2; ++rs) {
                    const int m = m0 + wm0 + mi * 16 + g + rs * 8;
                    float2 o;
                    o.x = acc[mi][nj][rs * 2]     + bj.x;
                    o.y = acc[mi][nj][rs * 2 + 1] + bj.y;
                    *(float2*)(C + (size_t)m * 1024 + col) = o;
                }
        }
    } else {
        const int nb   = n0 + wn0;
        const int part = nb >> 10;              // 0=q 1=k 2=v
        const int h    = (nb >> 6) & 15;
        const int bb   = m0 >> 11;
        const int sbq  = m0 & 2047;
        const size_t hb = (size_t)(bb * NH + h) * SEQ;

        float2 bj[8];
        #pragma unroll
        for (int j = 0; j < 8; ++j)
            bj[j] = *(const float2*)(bias + nb + j * 8 + 2 * t4);

        if (part == 2) {
            #pragma unroll
            for (int mi = 0; mi < 2; ++mi)
                #pragma unroll
                for (int rs = 0; rs < 2; ++rs) {
                    const int s = sbq + wm0 + mi * 16 + g + rs * 8;
                    __half* o = g_vh + (hb + s) * HDIM;
                    #pragma unroll
                    for (int j = 0; j < 8; ++j) {
                        uint32_t p = packh2(acc[mi][j][rs * 2 + 1] + bj[j].y,
                                            acc[mi][j][rs * 2]     + bj[j].x);
                        *(uint32_t*)(o + j * 8 + 2 * t4) = p;
                    }
                }
        } else {
            __half* dst = (part == 0) ? g_qh : g_kh;
            const float fac = (part == 0) ? QFAC : 1.0f;
            #pragma unroll
            for (int mi = 0; mi < 2; ++mi)
                #pragma unroll
                for (int rs = 0; rs < 2; ++rs) {
                    const int s = sbq + wm0 + mi * 16 + g + rs * 8;
                    __half* o = dst + (hb + s) * HDIM;
                    #pragma unroll
                    for (int j = 0; j < 4; ++j) {
                        const int f = j * 8 + 2 * t4;       // 0..31
                        const float2 cv = *(const float2*)(g_cos + s * 32 + f);
                        const float2 sv = *(const float2*)(g_sin + s * 32 + f);
                        const float x1a = acc[mi][j][rs * 2]         + bj[j].x;
                        const float x1b = acc[mi][j][rs * 2 + 1]     + bj[j].y;
                        const float x2a = acc[mi][j + 4][rs * 2]     + bj[j + 4].x;
                        const float x2b = acc[mi][j + 4][rs * 2 + 1] + bj[j + 4].y;
                        uint32_t lo = packh2((x1b * cv.y - x2b * sv.y) * fac,
                                             (x1a * cv.x - x2a * sv.x) * fac);
                        uint32_t hi = packh2((x1b * sv.y + x2b * cv.y) * fac,
                                             (x1a * sv.x + x2a * cv.x) * fac);
                        *(uint32_t*)(o + f)      = lo;
                        *(uint32_t*)(o + f + 32) = hi;
                    }
                }
        }
    }
}

// ---------------- fp16 flash attention, phase-split softmax ------------------
// Max-free softmax; QK^T with fp16 accumulators. NEW: both 64-col passes'
// QK MMAs run first, then both exp2 blocks, then both PV blocks — the
// second exp block is independent of the first PV block, so the scheduler
// can feed the tensor pipe during MUFU work (one exp stage leaves the
// per-kt critical path). smem 112KB, 8 warps, 2 CTAs/SM.
__global__ void __launch_bounds__(256, 2)
attn_h()
{
    const uint32_t sb = smem_u32(dyn_sm);
    const int tid  = threadIdx.x;
    const int w    = tid >> 5;
    const int lane = tid & 31;
    const int g    = lane >> 2;
    const int t4   = lane & 3;
    const int qt   = blockIdx.x;
    const int bh   = blockIdx.y;
    const size_t hb = (size_t)bh * SEQ * HDIM;
    const int wq0  = w * 16;            // warp's 16 q-rows

    const int crow = tid >> 3;          // 0..31 staging base row
    const int cch  = tid & 7;

    const int lrA = (lane & 7) + ((lane >> 3) & 1) * 8;
    const int lhA = lane >> 4;
    const int lrB = (lane & 7) + ((lane >> 4) & 1) * 8;
    const int lhB = (lane >> 3) & 1;

    const uint32_t ONES = 0x3C003C00u;  // fp16x2 {1.0, 1.0}

    const __half* ksrc0 = g_kh + hb + cch * 8;
    const __half* vsrc0 = g_vh + hb + cch * 8;

    // prologue: group0 = Q + K0/V0 (128 rows each); group1 = K1/V1
    {
        const __half* qsrc = g_qh + hb + (size_t)qt * 128 * HDIM + cch * 8;
        #pragma unroll
        for (int r = 0; r < 4; ++r) {
            int row = crow + 32 * r;
            cpa16(sb + swz(row, cch), qsrc + (size_t)row * HDIM);
        }
        #pragma unroll
        for (int r = 0; r < 4; ++r) {
            int row = crow + 32 * r;
            cpa16(sb + 16384u + swz(row, cch), ksrc0 + (size_t)row * HDIM);
            cpa16(sb + 65536u + swz(row, cch), vsrc0 + (size_t)row * HDIM);
        }
        CP_COMMIT();
        #pragma unroll
        for (int r = 0; r < 4; ++r) {
            int row = crow + 32 * r;
            cpa16(sb + 16384u + 16384u + swz(row, cch), ksrc0 + (size_t)(128 + row) * HDIM);
            cpa16(sb + 65536u + 16384u + swz(row, cch), vsrc0 + (size_t)(128 + row) * HDIM);
        }
        CP_COMMIT();
    }

    float O[8][4] = {};
    float lacc[4] = {};                 // row sums via ones-MMA
    uint32_t qf[4][4];                  // Q A-frags, preloaded once

    #pragma unroll 1
    for (int kt = 0; kt < 16; ++kt) {
        cp_wait<1>();
        __syncthreads();

        // issue stage kt+2 (buffer (kt+2)%3 last read in iter kt-1)
        if (kt + 2 < 16) {
            const uint32_t bo = (uint32_t)((kt + 2) % 3) * 16384u;
            const size_t go = (size_t)(kt + 2) * 128 * HDIM;
            #pragma unroll
            for (int r = 0; r < 4; ++r) {
                int row = crow + 32 * r;
                cpa16(sb + 16384u + bo + swz(row, cch), ksrc0 + go + (size_t)row * HDIM);
                cpa16(sb + 65536u + bo + swz(row, cch), vsrc0 + go + (size_t)row * HDIM);
            }
        }
        CP_COMMIT();

        if (kt == 0) {
            #pragma unroll
            for (int kc = 0; kc < 4; ++kc)
                ldsm4(qf[kc], sb + swz(wq0 + lrA, kc * 2 + lhA));
        }

        const uint32_t Ks = sb + 16384u + (uint32_t)(kt % 3) * 16384u;
        const uint32_t Vs = sb + 65536u + (uint32_t)(kt % 3) * 16384u;

        // ---- phase 1: S = Q K^T for BOTH 64-col passes (fp16 accum) ----
        uint32_t scp[2][8][2] = {};     // [hf][nj][rowsel]
        #pragma unroll
        for (int hf = 0; hf < 2; ++hf) {
            const int rb = hf * 64;
            #pragma unroll
            for (int kc = 0; kc < 4; ++kc) {
                #pragma unroll
                for (int np = 0; np < 4; ++np) {
                    uint32_t b4[4];
                    ldsm4(b4, Ks + swz(rb + np * 16 + lrB, kc * 2 + lhB));
                    mma16816h(scp[hf][2 * np],     qf[kc], b4[0], b4[1]);
                    mma16816h(scp[hf][2 * np + 1], qf[kc], b4[2], b4[3]);
                }
            }
        }

        // ---- phase 2: P = exp2(S), both passes ----
        #pragma unroll
        for (int hf = 0; hf < 2; ++hf)
            #pragma unroll
            for (int j = 0; j < 8; ++j) {
                scp[hf][j][0] = h2exp2(scp[hf][j][0]);
                scp[hf][j][1] = h2exp2(scp[hf][j][1]);
            }

        // ---- phase 3: O += P V ; l += P * ones, both passes ----
        #pragma unroll
        for (int hf = 0; hf < 2; ++hf) {
            const int rb = hf * 64;
            #pragma unroll
            for (int kc = 0; kc < 4; ++kc) {
                uint32_t pa[4];
                pa[0] = scp[hf][2 * kc][0];
                pa[1] = scp[hf][2 * kc][1];
                pa[2] = scp[hf][2 * kc + 1][0];
                pa[3] = scp[hf][2 * kc + 1][1];
                mma16816(lacc, pa, ONES, ONES);
                #pragma unroll
                for (int np = 0; np < 4; ++np) {
                    uint32_t v4[4];
                    ldsm4t(v4, Vs + swz(rb + kc * 16 + lrA, np * 2 + lhA));
                    mma16816(O[2 * np],     pa, v4[0], v4[1]);
                    mma16816(O[2 * np + 1], pa, v4[2], v4[3]);
                }
            }
        }
    }

    // ---- epilogue: O/l -> fp16 -> g_attn_h [b*S+s][h*64+d] ----
    const int bb = bh >> 4;
    const int h  = bh & 15;
    const float inv0 = 1.0f / lacc[0];          // row g
    const float inv1 = 1.0f / lacc[2];          // row g+8
    #pragma unroll
    for (int rs = 0; rs < 2; ++rs) {
        const float inv = rs ? inv1 : inv0;
        const int s = qt * 128 + wq0 + g + rs * 8;
        __half* o = g_attn_h + (size_t)(bb * SEQ + s) * DIM + h * HDIM;
        #pragma unroll
        for (int j = 0; j < 8; ++j) {
            uint32_t p = packh2(O[j][rs * 2 + 1] * inv,
                                O[j][rs * 2]     * inv);
            *(uint32_t*)(o + j * 8 + 2 * t4) = p;
        }
    }
}

// ---------------- launcher ----------------------------------------------------
extern "C" void kernel_launch(void* const* d_in, const int* in_sizes, int n_in,
                              void* d_out, int out_size)
{
    const float* hidden = (const float*)d_in[0];
    const float* Wqkv_w = (const float*)d_in[1];
    const float* Wqkv_b = (const float*)d_in[2];
    const float* Wo_w   = (const float*)d_in[3];
    const float* Wo_b   = (const float*)d_in[4];
    float* out = (float*)d_out;

    static int attr_done = 0;
    if (!attr_done) {
        cudaFuncSetAttribute(gemm_h<0>, cudaFuncAttributeMaxDynamicSharedMemorySize, 65536);
        cudaFuncSetAttribute(gemm_h<1>, cudaFuncAttributeMaxDynamicSharedMemorySize, 65536);
        cudaFuncSetAttribute(attn_h,    cudaFuncAttributeMaxDynamicSharedMemorySize, 114688);
        attr_done = 1;
    }

    rope_table_kernel<<<(SEQ*32)/256, 256>>>();
    f2h_all<<<N4_ALL / (256 * 4), 256>>>(hidden, Wqkv_w, Wo_w);

    // QKV GEMM + bias + RoPE scatter (fp16 out): tiles 128x128
    gemm_h<1><<<dim3(NQKV/128, MTOT/128), 256, 65536>>>(Wqkv_b, nullptr);

    // flash attention: 64 heads x 16 q-tiles of 128 rows, 8 warps/CTA
    attn_h<<<dim3(SEQ/128, BATCH*NH), 256, 114688>>>();

    // output projection (fp32 out): tiles 128x128
    gemm_h<0><<<dim3(DIM/128, MTOT/128), 256, 65536>>>(Wo_b, out);
}

// round 16
// speedup vs baseline: 1.0071x; 1.0071x over previous
#include <cuda_runtime.h>
#include <cuda_fp16.h>
#include <math.h>
#include <stdint.h>

#define BATCH 4
#define SEQ   2048
#define DIM   1024
#define NH    16
#define HDIM  64
#define MTOT  (BATCH*SEQ)     // 8192
#define NQKV  (3*DIM)         // 3072

// ---------------- scratch (device globals; no allocations allowed) ----------
static __device__ __half g_hid_h[(size_t)MTOT*DIM];
static __device__ __half g_wqkv_h[(size_t)NQKV*DIM];
static __device__ __half g_wo_h[(size_t)DIM*DIM];
static __device__ __half g_qh[(size_t)BATCH*NH*SEQ*HDIM];   // [bh][s][d] (scaled)
static __device__ __half g_kh[(size_t)BATCH*NH*SEQ*HDIM];   // [bh][s][d]
static __device__ __half g_vh[(size_t)BATCH*NH*SEQ*HDIM];   // [bh][s][d]
static __device__ __half g_attn_h[(size_t)MTOT*DIM];        // [b*S+s][h*64+d]
static __device__ float  g_cos[SEQ*32];
static __device__ float  g_sin[SEQ*32];

// scale folded into Q: (1/sqrt(64)) * log2(e)
#define QFAC 0.18033688011112042f

// ---------------- small kernels ----------------------------------------------
__global__ void rope_table_kernel() {
    int idx = blockIdx.x * blockDim.x + threadIdx.x;
    if (idx >= SEQ*32) return;
    int s = idx >> 5;
    int f = idx & 31;
    float inv_freq = (float)exp(-((double)(2*f) / 64.0) * log(10000.0));
    float ang = (float)s * inv_freq;
    float sn, cs;
    sincosf(ang, &sn, &cs);
    g_cos[idx] = cs;
    g_sin[idx] = sn;
}

// merged fp32 -> fp16 bulk convert, MLP=4 (hidden | Wqkv | Wo)
#define N4_HID  (MTOT*DIM/4)
#define N4_WQKV (NQKV*DIM/4)
#define N4_WO   (DIM*DIM/4)
#define N4_ALL  (N4_HID + N4_WQKV + N4_WO)      // 3145728
__global__ void f2h_all(const float* __restrict__ hid,
                        const float* __restrict__ wq,
                        const float* __restrict__ wo) {
    const int base = blockIdx.x * (256 * 4) + threadIdx.x;
    float4 v[4];
    __half* dsts[4];
    int js[4];
    #pragma unroll
    for (int u = 0; u < 4; ++u) {
        int j = base + u * 256;
        const float* src; __half* dst;
        if (j < N4_HID)                   { src = hid; dst = g_hid_h; }
        else if ((j -= N4_HID) < N4_WQKV) { src = wq;  dst = g_wqkv_h; }
        else { j -= N4_WQKV;                src = wo;  dst = g_wo_h; }
        dsts[u] = dst; js[u] = j;
        v[u] = ((const float4*)src)[j];
    }
    #pragma unroll
    for (int u = 0; u < 4; ++u) {
        __half2 h0 = __floats2half2_rn(v[u].x, v[u].y);
        __half2 h1 = __floats2half2_rn(v[u].z, v[u].w);
        ((uint2*)dsts[u])[js[u]] = make_uint2(*(uint32_t*)&h0, *(uint32_t*)&h1);
    }
}

// ---------------- asm helpers -------------------------------------------------
__device__ __forceinline__ uint32_t smem_u32(const void* p) {
    uint32_t a;
    asm("{ .reg .u64 t; cvta.to.shared.u64 t, %1; cvt.u32.u64 %0, t; }" : "=r"(a) : "l"(p));
    return a;
}
__device__ __forceinline__ uint32_t packh2(float hi, float lo) {
    uint32_t r;
    asm("cvt.rn.f16x2.f32 %0, %1, %2;" : "=r"(r) : "f"(hi), "f"(lo));
    return r;
}
__device__ __forceinline__ uint32_t h2exp2(uint32_t x) {
    uint32_t y;
    asm("ex2.approx.f16x2 %0, %1;" : "=r"(y) : "r"(x));
    return y;
}
__device__ __forceinline__ void mma16816(float c[4], const uint32_t a[4],
                                         uint32_t b0, uint32_t b1) {
    asm volatile(
        "mma.sync.aligned.m16n8k16.row.col.f32.f16.f16.f32 "
        "{%0,%1,%2,%3},{%4,%5,%6,%7},{%8,%9},{%0,%1,%2,%3};"
        : "+f"(c[0]), "+f"(c[1]), "+f"(c[2]), "+f"(c[3])
        : "r"(a[0]), "r"(a[1]), "r"(a[2]), "r"(a[3]), "r"(b0), "r"(b1));
}
__device__ __forceinline__ void mma16816h(uint32_t c[2], const uint32_t a[4],
                                          uint32_t b0, uint32_t b1) {
    asm volatile(
        "mma.sync.aligned.m16n8k16.row.col.f16.f16.f16.f16 "
        "{%0,%1},{%2,%3,%4,%5},{%6,%7},{%0,%1};"
        : "+r"(c[0]), "+r"(c[1])
        : "r"(a[0]), "r"(a[1]), "r"(a[2]), "r"(a[3]), "r"(b0), "r"(b1));
}
__device__ __forceinline__ void ldsm4(uint32_t r[4], uint32_t addr) {
    asm volatile("ldmatrix.sync.aligned.m8n8.x4.shared.b16 {%0,%1,%2,%3}, [%4];"
        : "=r"(r[0]), "=r"(r[1]), "=r"(r[2]), "=r"(r[3]) : "r"(addr));
}
__device__ __forceinline__ void ldsm4t(uint32_t r[4], uint32_t addr) {
    asm volatile("ldmatrix.sync.aligned.m8n8.x4.trans.shared.b16 {%0,%1,%2,%3}, [%4];"
        : "=r"(r[0]), "=r"(r[1]), "=r"(r[2]), "=r"(r[3]) : "r"(addr));
}
__device__ __forceinline__ void cpa16(uint32_t dst, const void* src) {
    asm volatile("cp.async.cg.shared.global [%0], [%1], 16;" :: "r"(dst), "l"(src));
}
#define CP_COMMIT() asm volatile("cp.async.commit_group;" ::: "memory")
template<int N> __device__ __forceinline__ void cp_wait() {
    asm volatile("cp.async.wait_group %0;" :: "n"(N) : "memory");
}

// smem tile: rows of 64 halves (128B), chunk(16B) swizzle: ch ^ (row&7)
__device__ __forceinline__ uint32_t swz(int row, int ch) {
    return (uint32_t)(row * 128 + ((ch ^ (row & 7)) << 4));
}

extern __shared__ char dyn_sm[];

// ---------------- fp16 tensor-core NT GEMM (round-11/14, known good) ---------
template<int MODE>
__global__ void __launch_bounds__(256, 2)
gemm_h(const float* __restrict__ bias, float* __restrict__ C)
{
    const __half* Ah = (MODE == 1) ? g_hid_h : g_attn_h;
    const __half* Bh = (MODE == 1) ? g_wqkv_h : g_wo_h;

    const uint32_t sb = smem_u32(dyn_sm);
    const int tid  = threadIdx.x;
    const int w    = tid >> 5;
    const int lane = tid & 31;
    const int g    = lane >> 2;
    const int t4   = lane & 3;
    const int wm0  = (w >> 1) * 32;
    const int wn0  = (w & 1) * 64;
    const int m0   = blockIdx.y * 128;
    const int n0   = blockIdx.x * 128;

    const int crow = tid >> 3;
    const int cch  = tid & 7;

    const int lrA = (lane & 7) + ((lane >> 3) & 1) * 8;
    const int lhA = lane >> 4;
    const int lrB = (lane & 7) + ((lane >> 4) & 1) * 8;
    const int lhB = (lane >> 3) & 1;

    float acc[2][8][4] = {};

    {
        #pragma unroll
        for (int r = 0; r < 4; ++r) {
            int row = crow + 32 * r;
            cpa16(sb + swz(row, cch),          Ah + (size_t)(m0 + row) * 1024 + cch * 8);
            cpa16(sb + 32768u + swz(row, cch), Bh + (size_t)(n0 + row) * 1024 + cch * 8);
        }
        CP_COMMIT();
    }

    #pragma unroll 1
    for (int it = 0; it < 16; ++it) {
        const int buf = it & 1;
        if (it < 15) {
            const int k0 = (it + 1) * 64;
            const uint32_t bo = (uint32_t)(buf ^ 1) * 16384u;
            #pragma unroll
            for (int r = 0; r < 4; ++r) {
                int row = crow + 32 * r;
                cpa16(sb + bo + swz(row, cch),
                      Ah + (size_t)(m0 + row) * 1024 + k0 + cch * 8);
                cpa16(sb + 32768u + bo + swz(row, cch),
                      Bh + (size_t)(n0 + row) * 1024 + k0 + cch * 8);
            }
            CP_COMMIT();
            cp_wait<1>();
        } else {
            cp_wait<0>();
        }
        __syncthreads();

        const uint32_t Ab = sb + (uint32_t)buf * 16384u;
        const uint32_t Bb = sb + 32768u + (uint32_t)buf * 16384u;
        #pragma unroll
        for (int kc = 0; kc < 4; ++kc) {
            uint32_t a[2][4];
            #pragma unroll
            for (int mi = 0; mi < 2; ++mi)
                ldsm4(a[mi], Ab + swz(wm0 + mi * 16 + lrA, kc * 2 + lhA));
            #pragma unroll
            for (int np = 0; np < 4; ++np) {
                uint32_t b4[4];
                ldsm4(b4, Bb + swz(wn0 + np * 16 + lrB, kc * 2 + lhB));
                #pragma unroll
                for (int mi = 0; mi < 2; ++mi) {
                    mma16816(acc[mi][2 * np],     a[mi], b4[0], b4[1]);
                    mma16816(acc[mi][2 * np + 1], a[mi], b4[2], b4[3]);
                }
            }
        }
        __syncthreads();
    }

    if (MODE == 0) {
        #pragma unroll
        for (int nj = 0; nj < 8; ++nj) {
            const int col = n0 + wn0 + nj * 8 + 2 * t4;
            const float2 bj = *(const float2*)(bias + col);
            #pragma unroll
            for (int mi = 0; mi < 2; ++mi)
                #pragma unroll
                for (int rs = 0; rs < 2; ++rs) {
                    const int m = m0 + wm0 + mi * 16 + g + rs * 8;
                    float2 o;
                    o.x = acc[mi][nj][rs * 2]     + bj.x;
                    o.y = acc[mi][nj][rs * 2 + 1] + bj.y;
                    *(float2*)(C + (size_t)m * 1024 + col) = o;
                }
        }
    } else {
        const int nb   = n0 + wn0;
        const int part = nb >> 10;
        const int h    = (nb >> 6) & 15;
        const int bb   = m0 >> 11;
        const int sbq  = m0 & 2047;
        const size_t hb = (size_t)(bb * NH + h) * SEQ;

        float2 bj[8];
        #pragma unroll
        for (int j = 0; j < 8; ++j)
            bj[j] = *(const float2*)(bias + nb + j * 8 + 2 * t4);

        if (part == 2) {
            #pragma unroll
            for (int mi = 0; mi < 2; ++mi)
                #pragma unroll
                for (int rs = 0; rs < 2; ++rs) {
                    const int s = sbq + wm0 + mi * 16 + g + rs * 8;
                    __half* o = g_vh + (hb + s) * HDIM;
                    #pragma unroll
                    for (int j = 0; j < 8; ++j) {
                        uint32_t p = packh2(acc[mi][j][rs * 2 + 1] + bj[j].y,
                                            acc[mi][j][rs * 2]     + bj[j].x);
                        *(uint32_t*)(o + j * 8 + 2 * t4) = p;
                    }
                }
        } else {
            __half* dst = (part == 0) ? g_qh : g_kh;
            const float fac = (part == 0) ? QFAC : 1.0f;
            #pragma unroll
            for (int mi = 0; mi < 2; ++mi)
                #pragma unroll
                for (int rs = 0; rs < 2; ++rs) {
                    const int s = sbq + wm0 + mi * 16 + g + rs * 8;
                    __half* o = dst + (hb + s) * HDIM;
                    #pragma unroll
                    for (int j = 0; j < 4; ++j) {
                        const int f = j * 8 + 2 * t4;
                        const float2 cv = *(const float2*)(g_cos + s * 32 + f);
                        const float2 sv = *(const float2*)(g_sin + s * 32 + f);
                        const float x1a = acc[mi][j][rs * 2]         + bj[j].x;
                        const float x1b = acc[mi][j][rs * 2 + 1]     + bj[j].y;
                        const float x2a = acc[mi][j + 4][rs * 2]     + bj[j + 4].x;
                        const float x2b = acc[mi][j + 4][rs * 2 + 1] + bj[j + 4].y;
                        uint32_t lo = packh2((x1b * cv.y - x2b * sv.y) * fac,
                                             (x1a * cv.x - x2a * sv.x) * fac);
                        uint32_t hi = packh2((x1b * sv.y + x2b * cv.y) * fac,
                                             (x1a * sv.x + x2a * cv.x) * fac);
                        *(uint32_t*)(o + f)      = lo;
                        *(uint32_t*)(o + f + 32) = hi;
                    }
                }
        }
    }
}

// ---------------- fp16 flash attention, exp-pipelined ------------------------
// Max-free softmax, fp16-accum QK. NEW: P is carried one 64-row chunk behind:
// iteration kt computes QK(kt) then PV(kt-1) interleaved (at kc granularity)
// with exp2(kt) — the MUFU work hides inside the PV MMA stream instead of
// sitting on the critical path. 4-deep K/V cp.async ring (64-row chunks).
// smem: Q 16KB, K 4x8KB @16384, V 4x8KB @49152 = 80KB. 8 warps, 2 CTAs/SM.
__global__ void __launch_bounds__(256, 2)
attn_h()
{
    const uint32_t sb = smem_u32(dyn_sm);
    const int tid  = threadIdx.x;
    const int w    = tid >> 5;
    const int lane = tid & 31;
    const int g    = lane >> 2;
    const int t4   = lane & 3;
    const int qt   = blockIdx.x;
    const int bh   = blockIdx.y;
    const size_t hb = (size_t)bh * SEQ * HDIM;
    const int wq0  = w * 16;

    const int crow = tid >> 3;          // 0..31
    const int cch  = tid & 7;

    const int lrA = (lane & 7) + ((lane >> 3) & 1) * 8;
    const int lhA = lane >> 4;
    const int lrB = (lane & 7) + ((lane >> 4) & 1) * 8;
    const int lhB = (lane >> 3) & 1;

    const uint32_t ONES = 0x3C003C00u;

    const __half* ksrc0 = g_kh + hb + cch * 8;
    const __half* vsrc0 = g_vh + hb + cch * 8;

    // stage a 64-row K/V chunk `c` into ring slot c%4 (2 cpa16 each per thread)
    #define STAGE_KV(c) do {                                                     \
        const uint32_t _bo = (uint32_t)((c) & 3) * 8192u;                        \
        const size_t _go = (size_t)(c) * 64 * HDIM;                              \
        cpa16(sb + 16384u + _bo + swz(crow, cch),      ksrc0 + _go + (size_t)crow * HDIM);        \
        cpa16(sb + 16384u + _bo + swz(crow + 32, cch), ksrc0 + _go + (size_t)(crow + 32) * HDIM); \
        cpa16(sb + 49152u + _bo + swz(crow, cch),      vsrc0 + _go + (size_t)crow * HDIM);        \
        cpa16(sb + 49152u + _bo + swz(crow + 32, cch), vsrc0 + _go + (size_t)(crow + 32) * HDIM); \
    } while (0)

    // prologue: G0 = Q + chunk0; G1 = chunk1; G2 = chunk2
    {
        const __half* qsrc = g_qh + hb + (size_t)qt * 128 * HDIM + cch * 8;
        #pragma unroll
        for (int r = 0; r < 4; ++r) {
            int row = crow + 32 * r;
            cpa16(sb + swz(row, cch), qsrc + (size_t)row * HDIM);
        }
        STAGE_KV(0);
        CP_COMMIT();
        STAGE_KV(1);
        CP_COMMIT();
        STAGE_KV(2);
        CP_COMMIT();
    }

    float O[8][4] = {};
    float lacc[4] = {};
    uint32_t qf[4][4];
    uint32_t s0[8][2], s1[8][2];        // two P generations (fp16x2 pairs)

    cp_wait<2>();                       // G0 done (Q + chunk0)
    __syncthreads();
    #pragma unroll
    for (int kc = 0; kc < 4; ++kc)
        ldsm4(qf[kc], sb + swz(wq0 + lrA, kc * 2 + lhA));

    // peel kt=0: QK + exp into s0
    {
        const uint32_t Ks = sb + 16384u;
        #pragma unroll
        for (int j = 0; j < 8; ++j) { s0[j][0] = 0u; s0[j][1] = 0u; }
        #pragma unroll
        for (int kc = 0; kc < 4; ++kc)
            #pragma unroll
            for (int np = 0; np < 4; ++np) {
                uint32_t b4[4];
                ldsm4(b4, Ks + swz(np * 16 + lrB, kc * 2 + lhB));
                mma16816h(s0[2 * np],     qf[kc], b4[0], b4[1]);
                mma16816h(s0[2 * np + 1], qf[kc], b4[2], b4[3]);
            }
        #pragma unroll
        for (int j = 0; j < 8; ++j) {
            s0[j][0] = h2exp2(s0[j][0]);
            s0[j][1] = h2exp2(s0[j][1]);
        }
        cp_wait<1>();                   // G1 (chunk1) done
    }

    // BODY(kt): barrier; prefetch kt+2; QK(kt)->CUR; PV(kt-1)[PREV] || exp(kt)
    #define BODY(kt, CUR, PREV) do {                                            \
        __syncthreads();                                                        \
        if ((kt) + 2 < 32) STAGE_KV((kt) + 2);                                  \
        CP_COMMIT();                                                            \
        const uint32_t Ks = sb + 16384u + (uint32_t)((kt) & 3) * 8192u;         \
        const uint32_t Vp = sb + 49152u + (uint32_t)(((kt) - 1) & 3) * 8192u;   \
        _Pragma("unroll")                                                       \
        for (int j = 0; j < 8; ++j) { CUR[j][0] = 0u; CUR[j][1] = 0u; }         \
        _Pragma("unroll")                                                       \
        for (int kc = 0; kc < 4; ++kc)                                          \
            _Pragma("unroll")                                                   \
            for (int np = 0; np < 4; ++np) {                                    \
                uint32_t b4[4];                                                 \
                ldsm4(b4, Ks + swz(np * 16 + lrB, kc * 2 + lhB));               \
                mma16816h(CUR[2 * np],     qf[kc], b4[0], b4[1]);               \
                mma16816h(CUR[2 * np + 1], qf[kc], b4[2], b4[3]);               \
            }                                                                   \
        _Pragma("unroll")                                                       \
        for (int kc = 0; kc < 4; ++kc) {                                        \
            CUR[2 * kc][0]     = h2exp2(CUR[2 * kc][0]);                        \
            CUR[2 * kc][1]     = h2exp2(CUR[2 * kc][1]);                        \
            CUR[2 * kc + 1][0] = h2exp2(CUR[2 * kc + 1][0]);                    \
            CUR[2 * kc + 1][1] = h2exp2(CUR[2 * kc + 1][1]);                    \
            uint32_t pa[4];                                                     \
            pa[0] = PREV[2 * kc][0];                                            \
            pa[1] = PREV[2 * kc][1];                                            \
            pa[2] = PREV[2 * kc + 1][0];                                        \
            pa[3] = PREV[2 * kc + 1][1];                                        \
            mma16816(lacc, pa, ONES, ONES);                                     \
            _Pragma("unroll")                                                   \
            for (int np = 0; np < 4; ++np) {                                    \
                uint32_t v4[4];                                                 \
                ldsm4t(v4, Vp + swz(kc * 16 + lrA, np * 2 + lhA));              \
                mma16816(O[2 * np],     pa, v4[0], v4[1]);                      \
                mma16816(O[2 * np + 1], pa, v4[2], v4[3]);                      \
            }                                                                   \
        }                                                                       \
        cp_wait<1>();                                                           \
    } while (0)

    // kt = 1..30 as 15 pairs, then kt = 31
    #pragma unroll 1
    for (int kt = 1; kt < 31; kt += 2) {
        BODY(kt,     s1, s0);
        BODY(kt + 1, s0, s1);
    }
    BODY(31, s1, s0);

    // tail: PV(31) from s1 (V chunk 31 still resident in slot 31&3)
    {
        const uint32_t Vp = sb + 49152u + (uint32_t)(31 & 3) * 8192u;
        #pragma unroll
        for (int kc = 0; kc < 4; ++kc) {
            uint32_t pa[4];
            pa[0] = s1[2 * kc][0];
            pa[1] = s1[2 * kc][1];
            pa[2] = s1[2 * kc + 1][0];
            pa[3] = s1[2 * kc + 1][1];
            mma16816(lacc, pa, ONES, ONES);
            #pragma unroll
            for (int np = 0; np < 4; ++np) {
                uint32_t v4[4];
                ldsm4t(v4, Vp + swz(kc * 16 + lrA, np * 2 + lhA));
                mma16816(O[2 * np],     pa, v4[0], v4[1]);
                mma16816(O[2 * np + 1], pa, v4[2], v4[3]);
            }
        }
    }

    // ---- epilogue: O/l -> fp16 -> g_attn_h [b*S+s][h*64+d] ----
    const int bb = bh >> 4;
    const int h  = bh & 15;
    const float inv0 = 1.0f / lacc[0];
    const float inv1 = 1.0f / lacc[2];
    #pragma unroll
    for (int rs = 0; rs < 2; ++rs) {
        const float inv = rs ? inv1 : inv0;
        const int s = qt * 128 + wq0 + g + rs * 8;
        __half* o = g_attn_h + (size_t)(bb * SEQ + s) * DIM + h * HDIM;
        #pragma unroll
        for (int j = 0; j < 8; ++j) {
            uint32_t p = packh2(O[j][rs * 2 + 1] * inv,
                                O[j][rs * 2]     * inv);
            *(uint32_t*)(o + j * 8 + 2 * t4) = p;
        }
    }
    #undef BODY
    #undef STAGE_KV
}

// ---------------- launcher ----------------------------------------------------
extern "C" void kernel_launch(void* const* d_in, const int* in_sizes, int n_in,
                              void* d_out, int out_size)
{
    const float* hidden = (const float*)d_in[0];
    const float* Wqkv_w = (const float*)d_in[1];
    const float* Wqkv_b = (const float*)d_in[2];
    const float* Wo_w   = (const float*)d_in[3];
    const float* Wo_b   = (const float*)d_in[4];
    float* out = (float*)d_out;

    static int attr_done = 0;
    if (!attr_done) {
        cudaFuncSetAttribute(gemm_h<0>, cudaFuncAttributeMaxDynamicSharedMemorySize, 65536);
        cudaFuncSetAttribute(gemm_h<1>, cudaFuncAttributeMaxDynamicSharedMemorySize, 65536);
        cudaFuncSetAttribute(attn_h,    cudaFuncAttributeMaxDynamicSharedMemorySize, 81920);
        attr_done = 1;
    }

    rope_table_kernel<<<(SEQ*32)/256, 256>>>();
    f2h_all<<<N4_ALL / (256 * 4), 256>>>(hidden, Wqkv_w, Wo_w);

    // QKV GEMM + bias + RoPE scatter (fp16 out): tiles 128x128
    gemm_h<1><<<dim3(NQKV/128, MTOT/128), 256, 65536>>>(Wqkv_b, nullptr);

    // flash attention: 64 heads x 16 q-tiles of 128 rows, 8 warps/CTA
    attn_h<<<dim3(SEQ/128, BATCH*NH), 256, 81920>>>();

    // output projection (fp32 out): tiles 128x128
    gemm_h<0><<<dim3(DIM/128, MTOT/128), 256, 65536>>>(Wo_b, out);
}

// round 17
// speedup vs baseline: 1.0194x; 1.0122x over previous
#include <cuda_runtime.h>
#include <cuda_fp16.h>
#include <math.h>
#include <stdint.h>

#define BATCH 4
#define SEQ   2048
#define DIM   1024
#define NH    16
#define HDIM  64
#define MTOT  (BATCH*SEQ)     // 8192
#define NQKV  (3*DIM)         // 3072

// ---------------- scratch (device globals; no allocations allowed) ----------
static __device__ __half g_hid_h[(size_t)MTOT*DIM];
static __device__ __half g_wqkv_h[(size_t)NQKV*DIM];
static __device__ __half g_wo_h[(size_t)DIM*DIM];
static __device__ __half g_qh[(size_t)BATCH*NH*SEQ*HDIM];   // [bh][s][d] (scaled)
static __device__ __half g_kh[(size_t)BATCH*NH*SEQ*HDIM];   // [bh][s][d]
static __device__ __half g_vh[(size_t)BATCH*NH*SEQ*HDIM];   // [bh][s][d]
static __device__ __half g_attn_h[(size_t)MTOT*DIM];        // [b*S+s][h*64+d]
static __device__ float  g_cos[SEQ*32];
static __device__ float  g_sin[SEQ*32];

// scale folded into Q: (1/sqrt(64)) * log2(e)
#define QFAC 0.18033688011112042f

// ---------------- small kernels ----------------------------------------------
__global__ void rope_table_kernel() {
    int idx = blockIdx.x * blockDim.x + threadIdx.x;
    if (idx >= SEQ*32) return;
    int s = idx >> 5;
    int f = idx & 31;
    float inv_freq = (float)exp(-((double)(2*f) / 64.0) * log(10000.0));
    float ang = (float)s * inv_freq;
    float sn, cs;
    sincosf(ang, &sn, &cs);
    g_cos[idx] = cs;
    g_sin[idx] = sn;
}

// merged fp32 -> fp16 bulk convert, MLP=4 (hidden | Wqkv | Wo)
#define N4_HID  (MTOT*DIM/4)
#define N4_WQKV (NQKV*DIM/4)
#define N4_WO   (DIM*DIM/4)
#define N4_ALL  (N4_HID + N4_WQKV + N4_WO)      // 3145728
__global__ void f2h_all(const float* __restrict__ hid,
                        const float* __restrict__ wq,
                        const float* __restrict__ wo) {
    const int base = blockIdx.x * (256 * 4) + threadIdx.x;
    float4 v[4];
    __half* dsts[4];
    int js[4];
    #pragma unroll
    for (int u = 0; u < 4; ++u) {
        int j = base + u * 256;
        const float* src; __half* dst;
        if (j < N4_HID)                   { src = hid; dst = g_hid_h; }
        else if ((j -= N4_HID) < N4_WQKV) { src = wq;  dst = g_wqkv_h; }
        else { j -= N4_WQKV;                src = wo;  dst = g_wo_h; }
        dsts[u] = dst; js[u] = j;
        v[u] = ((const float4*)src)[j];
    }
    #pragma unroll
    for (int u = 0; u < 4; ++u) {
        __half2 h0 = __floats2half2_rn(v[u].x, v[u].y);
        __half2 h1 = __floats2half2_rn(v[u].z, v[u].w);
        ((uint2*)dsts[u])[js[u]] = make_uint2(*(uint32_t*)&h0, *(uint32_t*)&h1);
    }
}

// ---------------- asm helpers -------------------------------------------------
__device__ __forceinline__ uint32_t smem_u32(const void* p) {
    uint32_t a;
    asm("{ .reg .u64 t; cvta.to.shared.u64 t, %1; cvt.u32.u64 %0, t; }" : "=r"(a) : "l"(p));
    return a;
}
__device__ __forceinline__ uint32_t packh2(float hi, float lo) {
    uint32_t r;
    asm("cvt.rn.f16x2.f32 %0, %1, %2;" : "=r"(r) : "f"(hi), "f"(lo));
    return r;
}
__device__ __forceinline__ uint32_t h2exp2(uint32_t x) {
    uint32_t y;
    asm("ex2.approx.f16x2 %0, %1;" : "=r"(y) : "r"(x));
    return y;
}
__device__ __forceinline__ uint32_t haddx2(uint32_t a, uint32_t b) {
    uint32_t r;
    asm("add.f16x2 %0, %1, %2;" : "=r"(r) : "r"(a), "r"(b));
    return r;
}
__device__ __forceinline__ void mma16816(float c[4], const uint32_t a[4],
                                         uint32_t b0, uint32_t b1) {
    asm volatile(
        "mma.sync.aligned.m16n8k16.row.col.f32.f16.f16.f32 "
        "{%0,%1,%2,%3},{%4,%5,%6,%7},{%8,%9},{%0,%1,%2,%3};"
        : "+f"(c[0]), "+f"(c[1]), "+f"(c[2]), "+f"(c[3])
        : "r"(a[0]), "r"(a[1]), "r"(a[2]), "r"(a[3]), "r"(b0), "r"(b1));
}
__device__ __forceinline__ void mma16816h(uint32_t c[2], const uint32_t a[4],
                                          uint32_t b0, uint32_t b1) {
    asm volatile(
        "mma.sync.aligned.m16n8k16.row.col.f16.f16.f16.f16 "
        "{%0,%1},{%2,%3,%4,%5},{%6,%7},{%0,%1};"
        : "+r"(c[0]), "+r"(c[1])
        : "r"(a[0]), "r"(a[1]), "r"(a[2]), "r"(a[3]), "r"(b0), "r"(b1));
}
__device__ __forceinline__ void ldsm4(uint32_t r[4], uint32_t addr) {
    asm volatile("ldmatrix.sync.aligned.m8n8.x4.shared.b16 {%0,%1,%2,%3}, [%4];"
        : "=r"(r[0]), "=r"(r[1]), "=r"(r[2]), "=r"(r[3]) : "r"(addr));
}
__device__ __forceinline__ void ldsm4t(uint32_t r[4], uint32_t addr) {
    asm volatile("ldmatrix.sync.aligned.m8n8.x4.trans.shared.b16 {%0,%1,%2,%3}, [%4];"
        : "=r"(r[0]), "=r"(r[1]), "=r"(r[2]), "=r"(r[3]) : "r"(addr));
}
__device__ __forceinline__ void cpa16(uint32_t dst, const void* src) {
    asm volatile("cp.async.cg.shared.global [%0], [%1], 16;" :: "r"(dst), "l"(src));
}
#define CP_COMMIT() asm volatile("cp.async.commit_group;" ::: "memory")
template<int N> __device__ __forceinline__ void cp_wait() {
    asm volatile("cp.async.wait_group %0;" :: "n"(N) : "memory");
}

// smem tile: rows of 64 halves (128B), chunk(16B) swizzle: ch ^ (row&7)
__device__ __forceinline__ uint32_t swz(int row, int ch) {
    return (uint32_t)(row * 128 + ((ch ^ (row & 7)) << 4));
}

extern __shared__ char dyn_sm[];

// ---------------- fp16 tensor-core NT GEMM (round-11/14, known good) ---------
template<int MODE>
__global__ void __launch_bounds__(256, 2)
gemm_h(const float* __restrict__ bias, float* __restrict__ C)
{
    const __half* Ah = (MODE == 1) ? g_hid_h : g_attn_h;
    const __half* Bh = (MODE == 1) ? g_wqkv_h : g_wo_h;

    const uint32_t sb = smem_u32(dyn_sm);
    const int tid  = threadIdx.x;
    const int w    = tid >> 5;
    const int lane = tid & 31;
    const int g    = lane >> 2;
    const int t4   = lane & 3;
    const int wm0  = (w >> 1) * 32;
    const int wn0  = (w & 1) * 64;
    const int m0   = blockIdx.y * 128;
    const int n0   = blockIdx.x * 128;

    const int crow = tid >> 3;
    const int cch  = tid & 7;

    const int lrA = (lane & 7) + ((lane >> 3) & 1) * 8;
    const int lhA = lane >> 4;
    const int lrB = (lane & 7) + ((lane >> 4) & 1) * 8;
    const int lhB = (lane >> 3) & 1;

    float acc[2][8][4] = {};

    {
        #pragma unroll
        for (int r = 0; r < 4; ++r) {
            int row = crow + 32 * r;
            cpa16(sb + swz(row, cch),          Ah + (size_t)(m0 + row) * 1024 + cch * 8);
            cpa16(sb + 32768u + swz(row, cch), Bh + (size_t)(n0 + row) * 1024 + cch * 8);
        }
        CP_COMMIT();
    }

    #pragma unroll 1
    for (int it = 0; it < 16; ++it) {
        const int buf = it & 1;
        if (it < 15) {
            const int k0 = (it + 1) * 64;
            const uint32_t bo = (uint32_t)(buf ^ 1) * 16384u;
            #pragma unroll
            for (int r = 0; r < 4; ++r) {
                int row = crow + 32 * r;
                cpa16(sb + bo + swz(row, cch),
                      Ah + (size_t)(m0 + row) * 1024 + k0 + cch * 8);
                cpa16(sb + 32768u + bo + swz(row, cch),
                      Bh + (size_t)(n0 + row) * 1024 + k0 + cch * 8);
            }
            CP_COMMIT();
            cp_wait<1>();
        } else {
            cp_wait<0>();
        }
        __syncthreads();

        const uint32_t Ab = sb + (uint32_t)buf * 16384u;
        const uint32_t Bb = sb + 32768u + (uint32_t)buf * 16384u;
        #pragma unroll
        for (int kc = 0; kc < 4; ++kc) {
            uint32_t a[2][4];
            #pragma unroll
            for (int mi = 0; mi < 2; ++mi)
                ldsm4(a[mi], Ab + swz(wm0 + mi * 16 + lrA, kc * 2 + lhA));
            #pragma unroll
            for (int np = 0; np < 4; ++np) {
                uint32_t b4[4];
                ldsm4(b4, Bb + swz(wn0 + np * 16 + lrB, kc * 2 + lhB));
                #pragma unroll
                for (int mi = 0; mi < 2; ++mi) {
                    mma16816(acc[mi][2 * np],     a[mi], b4[0], b4[1]);
                    mma16816(acc[mi][2 * np + 1], a[mi], b4[2], b4[3]);
                }
            }
        }
        __syncthreads();
    }

    if (MODE == 0) {
        #pragma unroll
        for (int nj = 0; nj < 8; ++nj) {
            const int col = n0 + wn0 + nj * 8 + 2 * t4;
            const float2 bj = *(const float2*)(bias + col);
            #pragma unroll
            for (int mi = 0; mi < 2; ++mi)
                #pragma unroll
                for (int rs = 0; rs < 2; ++rs) {
                    const int m = m0 + wm0 + mi * 16 + g + rs * 8;
                    float2 o;
                    o.x = acc[mi][nj][rs * 2]     + bj.x;
                    o.y = acc[mi][nj][rs * 2 + 1] + bj.y;
                    *(float2*)(C + (size_t)m * 1024 + col) = o;
                }
        }
    } else {
        const int nb   = n0 + wn0;
        const int part = nb >> 10;
        const int h    = (nb >> 6) & 15;
        const int bb   = m0 >> 11;
        const int sbq  = m0 & 2047;
        const size_t hb = (size_t)(bb * NH + h) * SEQ;

        float2 bj[8];
        #pragma unroll
        for (int j = 0; j < 8; ++j)
            bj[j] = *(const float2*)(bias + nb + j * 8 + 2 * t4);

        if (part == 2) {
            #pragma unroll
            for (int mi = 0; mi < 2; ++mi)
                #pragma unroll
                for (int rs = 0; rs < 2; ++rs) {
                    const int s = sbq + wm0 + mi * 16 + g + rs * 8;
                    __half* o = g_vh + (hb + s) * HDIM;
                    #pragma unroll
                    for (int j = 0; j < 8; ++j) {
                        uint32_t p = packh2(acc[mi][j][rs * 2 + 1] + bj[j].y,
                                            acc[mi][j][rs * 2]     + bj[j].x);
                        *(uint32_t*)(o + j * 8 + 2 * t4) = p;
                    }
                }
        } else {
            __half* dst = (part == 0) ? g_qh : g_kh;
            const float fac = (part == 0) ? QFAC : 1.0f;
            #pragma unroll
            for (int mi = 0; mi < 2; ++mi)
                #pragma unroll
                for (int rs = 0; rs < 2; ++rs) {
                    const int s = sbq + wm0 + mi * 16 + g + rs * 8;
                    __half* o = dst + (hb + s) * HDIM;
                    #pragma unroll
                    for (int j = 0; j < 4; ++j) {
                        const int f = j * 8 + 2 * t4;
                        const float2 cv = *(const float2*)(g_cos + s * 32 + f);
                        const float2 sv = *(const float2*)(g_sin + s * 32 + f);
                        const float x1a = acc[mi][j][rs * 2]         + bj[j].x;
                        const float x1b = acc[mi][j][rs * 2 + 1]     + bj[j].y;
                        const float x2a = acc[mi][j + 4][rs * 2]     + bj[j + 4].x;
                        const float x2b = acc[mi][j + 4][rs * 2 + 1] + bj[j + 4].y;
                        uint32_t lo = packh2((x1b * cv.y - x2b * sv.y) * fac,
                                             (x1a * cv.x - x2a * sv.x) * fac);
                        uint32_t hi = packh2((x1b * sv.y + x2b * cv.y) * fac,
                                             (x1a * sv.x + x2a * cv.x) * fac);
                        *(uint32_t*)(o + f)      = lo;
                        *(uint32_t*)(o + f + 32) = hi;
                    }
                }
        }
    }
}

// ---------------- fp16 flash attention, exp-pipelined, ALU row-sums ----------
// Max-free softmax, fp16-accum QK, P carried one chunk behind (r16).
// NEW: row sums l computed with add.f16x2 reductions on the ALU pipe
// (per-lane fp32 partials, single quad-shuffle reduce in the epilogue)
// instead of ones-MMAs — removes 4/68 HMMA per warp-chunk from the
// tensor pipe. smem: Q 16KB, K 4x8KB @16384, V 4x8KB @49152 = 80KB.
__global__ void __launch_bounds__(256, 2)
attn_h()
{
    const uint32_t sb = smem_u32(dyn_sm);
    const int tid  = threadIdx.x;
    const int w    = tid >> 5;
    const int lane = tid & 31;
    const int g    = lane >> 2;
    const int t4   = lane & 3;
    const int qt   = blockIdx.x;
    const int bh   = blockIdx.y;
    const size_t hb = (size_t)bh * SEQ * HDIM;
    const int wq0  = w * 16;

    const int crow = tid >> 3;          // 0..31
    const int cch  = tid & 7;

    const int lrA = (lane & 7) + ((lane >> 3) & 1) * 8;
    const int lhA = lane >> 4;
    const int lrB = (lane & 7) + ((lane >> 4) & 1) * 8;
    const int lhB = (lane >> 3) & 1;

    const __half* ksrc0 = g_kh + hb + cch * 8;
    const __half* vsrc0 = g_vh + hb + cch * 8;

    #define STAGE_KV(c) do {                                                     \
        const uint32_t _bo = (uint32_t)((c) & 3) * 8192u;                        \
        const size_t _go = (size_t)(c) * 64 * HDIM;                              \
        cpa16(sb + 16384u + _bo + swz(crow, cch),      ksrc0 + _go + (size_t)crow * HDIM);        \
        cpa16(sb + 16384u + _bo + swz(crow + 32, cch), ksrc0 + _go + (size_t)(crow + 32) * HDIM); \
        cpa16(sb + 49152u + _bo + swz(crow, cch),      vsrc0 + _go + (size_t)crow * HDIM);        \
        cpa16(sb + 49152u + _bo + swz(crow + 32, cch), vsrc0 + _go + (size_t)(crow + 32) * HDIM); \
    } while (0)

    // prologue: G0 = Q + chunk0; G1 = chunk1; G2 = chunk2
    {
        const __half* qsrc = g_qh + hb + (size_t)qt * 128 * HDIM + cch * 8;
        #pragma unroll
        for (int r = 0; r < 4; ++r) {
            int row = crow + 32 * r;
            cpa16(sb + swz(row, cch), qsrc + (size_t)row * HDIM);
        }
        STAGE_KV(0);
        CP_COMMIT();
        STAGE_KV(1);
        CP_COMMIT();
        STAGE_KV(2);
        CP_COMMIT();
    }

    float O[8][4] = {};
    float l0 = 0.f, l1 = 0.f;           // per-lane partial row sums (cols 2t4,2t4+1 ... )
    uint32_t qf[4][4];
    uint32_t s0[8][2], s1[8][2];

    cp_wait<2>();
    __syncthreads();
    #pragma unroll
    for (int kc = 0; kc < 4; ++kc)
        ldsm4(qf[kc], sb + swz(wq0 + lrA, kc * 2 + lhA));

    // peel kt=0: QK + exp into s0
    {
        const uint32_t Ks = sb + 16384u;
        #pragma unroll
        for (int j = 0; j < 8; ++j) { s0[j][0] = 0u; s0[j][1] = 0u; }
        #pragma unroll
        for (int kc = 0; kc < 4; ++kc)
            #pragma unroll
            for (int np = 0; np < 4; ++np) {
                uint32_t b4[4];
                ldsm4(b4, Ks + swz(np * 16 + lrB, kc * 2 + lhB));
                mma16816h(s0[2 * np],     qf[kc], b4[0], b4[1]);
                mma16816h(s0[2 * np + 1], qf[kc], b4[2], b4[3]);
            }
        #pragma unroll
        for (int j = 0; j < 8; ++j) {
            s0[j][0] = h2exp2(s0[j][0]);
            s0[j][1] = h2exp2(s0[j][1]);
        }
        cp_wait<1>();
    }

    // row-sum of a P generation (8 f16x2 per row) into fp32 partials (ALU pipe)
    #define LSUM(P) do {                                                        \
        uint32_t _h0 = haddx2(P[0][0], P[1][0]);                                \
        uint32_t _h1 = haddx2(P[0][1], P[1][1]);                                \
        _h0 = haddx2(_h0, haddx2(P[2][0], P[3][0]));                            \
        _h1 = haddx2(_h1, haddx2(P[2][1], P[3][1]));                            \
        _h0 = haddx2(_h0, haddx2(haddx2(P[4][0], P[5][0]), haddx2(P[6][0], P[7][0]))); \
        _h1 = haddx2(_h1, haddx2(haddx2(P[4][1], P[5][1]), haddx2(P[6][1], P[7][1]))); \
        float2 _f0 = __half22float2(*(__half2*)&_h0);                           \
        float2 _f1 = __half22float2(*(__half2*)&_h1);                           \
        l0 += _f0.x + _f0.y;                                                    \
        l1 += _f1.x + _f1.y;                                                    \
    } while (0)

    // BODY(kt): barrier; prefetch kt+2; QK(kt)->CUR; PV(kt-1)[PREV] || exp(kt)
    #define BODY(kt, CUR, PREV) do {                                            \
        __syncthreads();                                                        \
        if ((kt) + 2 < 32) STAGE_KV((kt) + 2);                                  \
        CP_COMMIT();                                                            \
        const uint32_t Ks = sb + 16384u + (uint32_t)((kt) & 3) * 8192u;         \
        const uint32_t Vp = sb + 49152u + (uint32_t)(((kt) - 1) & 3) * 8192u;   \
        _Pragma("unroll")                                                       \
        for (int j = 0; j < 8; ++j) { CUR[j][0] = 0u; CUR[j][1] = 0u; }         \
        _Pragma("unroll")                                                       \
        for (int kc = 0; kc < 4; ++kc)                                          \
            _Pragma("unroll")                                                   \
            for (int np = 0; np < 4; ++np) {                                    \
                uint32_t b4[4];                                                 \
                ldsm4(b4, Ks + swz(np * 16 + lrB, kc * 2 + lhB));               \
                mma16816h(CUR[2 * np],     qf[kc], b4[0], b4[1]);               \
                mma16816h(CUR[2 * np + 1], qf[kc], b4[2], b4[3]);               \
            }                                                                   \
        LSUM(PREV);                                                             \
        _Pragma("unroll")                                                       \
        for (int kc = 0; kc < 4; ++kc) {                                        \
            CUR[2 * kc][0]     = h2exp2(CUR[2 * kc][0]);                        \
            CUR[2 * kc][1]     = h2exp2(CUR[2 * kc][1]);                        \
            CUR[2 * kc + 1][0] = h2exp2(CUR[2 * kc + 1][0]);                    \
            CUR[2 * kc + 1][1] = h2exp2(CUR[2 * kc + 1][1]);                    \
            uint32_t pa[4];                                                     \
            pa[0] = PREV[2 * kc][0];                                            \
            pa[1] = PREV[2 * kc][1];                                            \
            pa[2] = PREV[2 * kc + 1][0];                                        \
            pa[3] = PREV[2 * kc + 1][1];                                        \
            _Pragma("unroll")                                                   \
            for (int np = 0; np < 4; ++np) {                                    \
                uint32_t v4[4];                                                 \
                ldsm4t(v4, Vp + swz(kc * 16 + lrA, np * 2 + lhA));              \
                mma16816(O[2 * np],     pa, v4[0], v4[1]);                      \
                mma16816(O[2 * np + 1], pa, v4[2], v4[3]);                      \
            }                                                                   \
        }                                                                       \
        cp_wait<1>();                                                           \
    } while (0)

    #pragma unroll 1
    for (int kt = 1; kt < 31; kt += 2) {
        BODY(kt,     s1, s0);
        BODY(kt + 1, s0, s1);
    }
    BODY(31, s1, s0);

    // tail: PV(31) from s1
    {
        const uint32_t Vp = sb + 49152u + (uint32_t)(31 & 3) * 8192u;
        LSUM(s1);
        #pragma unroll
        for (int kc = 0; kc < 4; ++kc) {
            uint32_t pa[4];
            pa[0] = s1[2 * kc][0];
            pa[1] = s1[2 * kc][1];
            pa[2] = s1[2 * kc + 1][0];
            pa[3] = s1[2 * kc + 1][1];
            #pragma unroll
            for (int np = 0; np < 4; ++np) {
                uint32_t v4[4];
                ldsm4t(v4, Vp + swz(kc * 16 + lrA, np * 2 + lhA));
                mma16816(O[2 * np],     pa, v4[0], v4[1]);
                mma16816(O[2 * np + 1], pa, v4[2], v4[3]);
            }
        }
    }

    // ---- epilogue: quad-reduce l, then O/l -> fp16 -> g_attn_h --------------
    l0 += __shfl_xor_sync(0xffffffffu, l0, 1);
    l0 += __shfl_xor_sync(0xffffffffu, l0, 2);
    l1 += __shfl_xor_sync(0xffffffffu, l1, 1);
    l1 += __shfl_xor_sync(0xffffffffu, l1, 2);

    const int bb = bh >> 4;
    const int h  = bh & 15;
    const float inv0 = 1.0f / l0;               // row g
    const float inv1 = 1.0f / l1;               // row g+8
    #pragma unroll
    for (int rs = 0; rs < 2; ++rs) {
        const float inv = rs ? inv1 : inv0;
        const int s = qt * 128 + wq0 + g + rs * 8;
        __half* o = g_attn_h + (size_t)(bb * SEQ + s) * DIM + h * HDIM;
        #pragma unroll
        for (int j = 0; j < 8; ++j) {
            uint32_t p = packh2(O[j][rs * 2 + 1] * inv,
                                O[j][rs * 2]     * inv);
            *(uint32_t*)(o + j * 8 + 2 * t4) = p;
        }
    }
    #undef BODY
    #undef LSUM
    #undef STAGE_KV
}

// ---------------- launcher ----------------------------------------------------
extern "C" void kernel_launch(void* const* d_in, const int* in_sizes, int n_in,
                              void* d_out, int out_size)
{
    const float* hidden = (const float*)d_in[0];
    const float* Wqkv_w = (const float*)d_in[1];
    const float* Wqkv_b = (const float*)d_in[2];
    const float* Wo_w   = (const float*)d_in[3];
    const float* Wo_b   = (const float*)d_in[4];
    float* out = (float*)d_out;

    static int attr_done = 0;
    if (!attr_done) {
        cudaFuncSetAttribute(gemm_h<0>, cudaFuncAttributeMaxDynamicSharedMemorySize, 65536);
        cudaFuncSetAttribute(gemm_h<1>, cudaFuncAttributeMaxDynamicSharedMemorySize, 65536);
        cudaFuncSetAttribute(attn_h,    cudaFuncAttributeMaxDynamicSharedMemorySize, 81920);
        attr_done = 1;
    }

    rope_table_kernel<<<(SEQ*32)/256, 256>>>();
    f2h_all<<<N4_ALL / (256 * 4), 256>>>(hidden, Wqkv_w, Wo_w);

    // QKV GEMM + bias + RoPE scatter (fp16 out): tiles 128x128
    gemm_h<1><<<dim3(NQKV/128, MTOT/128), 256, 65536>>>(Wqkv_b, nullptr);

    // flash attention: 64 heads x 16 q-tiles of 128 rows, 8 warps/CTA
    attn_h<<<dim3(SEQ/128, BATCH*NH), 256, 81920>>>();

    // output projection (fp32 out): tiles 128x128
    gemm_h<0><<<dim3(DIM/128, MTOT/128), 256, 65536>>>(Wo_b, out);
}